// round 14
// baseline (speedup 1.0000x reference)
#include <cuda_runtime.h>
#include <cstdint>
#include <math.h>

#define NEG_F (-3.402823466e+38f)   // jnp.finfo(float32).min == -FLT_MAX

// ---------------------------------------------------------------------------
// FINAL champion: one block per row i of the N x N mask (N = t*h*w).
//   Prologue: threads 0..130 load t/h/w and fully decode their candidate
//             column BEFORE the fill (latency overlaps the store stream).
//   Phase 1:  stream the row with -FLT_MAX via st.global.cs (evict-first) —
//             zero-reuse data; streaming hint smooths L2 writeback.
//   Phase 2:  after __syncthreads, candidate threads store 0.0f with default
//             policy (merges with the still-dirty L2 line; no extra DRAM).
// Masked columns per row:
//   - local window: dt,dh,dw in [-2,2]                      -> 125 candidates
//   - sparse pow2 {1,2,4} along exactly one axis (others 0) -> only +/-4 adds
//     new entries (1,2 lie inside the window)               ->   6 candidates
//
// Measured: 37.3-37.5us kernel = 7.2 TB/s sustained stores (90% of HBM spec).
// Benched and rejected: persistent grid (-27%), cp.async.bulk S2G (-16%;
// LTS cap is path-independent), STG.256 (neutral), branch-free per-chunk
// classify (-6%), 2 rows/block (neutral). At the DRAM-write roofline.
// ---------------------------------------------------------------------------
__global__ void __launch_bounds__(256)
fused_mask_kernel(const int* __restrict__ tp, const int* __restrict__ hp,
                  const int* __restrict__ wp, float4* __restrict__ out4, int N) {
    const int i   = blockIdx.x;         // row index
    const int tid = threadIdx.x;
    const int n4  = N >> 2;             // float4s per row
    float4* row = out4 + (size_t)i * (size_t)n4;

    // ---- Prologue: decode candidate before the fill (tid < 131) ----
    int j = -1;                         // column to zero; -1 = none
    if (tid < 131) {
        const int t = *tp;
        const int h = *hp;
        const int w = *wp;

        const int wi = i % w;
        const int ri = i / w;
        const int hi = ri % h;
        const int ti = ri / h;

        int dt, dh, dw;
        if (tid < 125) {
            dt = tid / 25 - 2;
            dh = (tid / 5) % 5 - 2;
            dw = tid % 5 - 2;
        } else {
            const int s    = tid - 125;        // 0..5
            const int axis = s >> 1;           // 0:t 1:h 2:w
            const int off  = (s & 1) ? 4 : -4;
            dt = (axis == 0) ? off : 0;
            dh = (axis == 1) ? off : 0;
            dw = (axis == 2) ? off : 0;
        }

        const int tj = ti + dt;
        const int hj = hi + dh;
        const int wj = wi + dw;
        if ((unsigned)tj < (unsigned)t &&
            (unsigned)hj < (unsigned)h &&
            (unsigned)wj < (unsigned)w) {
            j = (tj * h + hj) * w + wj;
        }
    }

    // ---- Phase 1: streaming fill with -FLT_MAX (evict-first) ----
    const float4 v = make_float4(NEG_F, NEG_F, NEG_F, NEG_F);
    #pragma unroll 8
    for (int f = tid; f < n4; f += 256) __stcs(row + f, v);

    __syncthreads();

    // ---- Phase 2: single store per candidate thread (default policy) ----
    if (j >= 0) ((float*)row)[j] = 0.0f;
}

// ---------------------------------------------------------------------------
extern "C" void kernel_launch(void* const* d_in, const int* in_sizes, int n_in,
                              void* d_out, int out_size) {
    const int N = (int)(sqrt((double)out_size) + 0.5);   // out is N*N floats

    const int* tp = (const int*)d_in[0];
    const int* hp = (const int*)d_in[1];
    const int* wp = (const int*)d_in[2];

    fused_mask_kernel<<<N, 256>>>(tp, hp, wp, (float4*)d_out, N);
}

// round 15
// speedup vs baseline: 1.0055x; 1.0055x over previous
#include <cuda_runtime.h>
#include <cstdint>
#include <math.h>

#define NEG_F (-3.402823466e+38f)   // jnp.finfo(float32).min == -FLT_MAX

// ---------------------------------------------------------------------------
// FINAL champion: one block per row i of the N x N mask (N = t*h*w).
//   Prologue: threads 0..130 load t/h/w and fully decode their candidate
//             column BEFORE the fill (latency overlaps the store stream).
//   Phase 1:  stream the row with -FLT_MAX via st.global.cs (evict-first) —
//             zero-reuse data; streaming hint smooths L2 writeback.
//   Phase 2:  after __syncthreads, candidate threads store 0.0f with default
//             policy (merges with the still-dirty L2 line; no extra DRAM).
// Masked columns per row:
//   - local window: dt,dh,dw in [-2,2]                      -> 125 candidates
//   - sparse pow2 {1,2,4} along exactly one axis (others 0) -> only +/-4 adds
//     new entries (1,2 lie inside the window)               ->   6 candidates
//
// Measured: ~37.5us kernel = 7.2 TB/s sustained stores (~90% of HBM spec).
// Benched and rejected: monolithic predicate (4x slower, ALU-bound),
// fill+scatter kernels (cold-RMW), persistent grid (-27%), cp.async.bulk
// S2G (-16%; LTS cap is path-independent), STG.256 (neutral), branch-free
// per-chunk classify (-6%), 2 rows/block (neutral).
// This kernel is at the DRAM-write roofline.
// ---------------------------------------------------------------------------
__global__ void __launch_bounds__(256)
fused_mask_kernel(const int* __restrict__ tp, const int* __restrict__ hp,
                  const int* __restrict__ wp, float4* __restrict__ out4, int N) {
    const int i   = blockIdx.x;         // row index
    const int tid = threadIdx.x;
    const int n4  = N >> 2;             // float4s per row
    float4* row = out4 + (size_t)i * (size_t)n4;

    // ---- Prologue: decode candidate before the fill (tid < 131) ----
    int j = -1;                         // column to zero; -1 = none
    if (tid < 131) {
        const int t = *tp;
        const int h = *hp;
        const int w = *wp;

        const int wi = i % w;
        const int ri = i / w;
        const int hi = ri % h;
        const int ti = ri / h;

        int dt, dh, dw;
        if (tid < 125) {
            dt = tid / 25 - 2;
            dh = (tid / 5) % 5 - 2;
            dw = tid % 5 - 2;
        } else {
            const int s    = tid - 125;        // 0..5
            const int axis = s >> 1;           // 0:t 1:h 2:w
            const int off  = (s & 1) ? 4 : -4;
            dt = (axis == 0) ? off : 0;
            dh = (axis == 1) ? off : 0;
            dw = (axis == 2) ? off : 0;
        }

        const int tj = ti + dt;
        const int hj = hi + dh;
        const int wj = wi + dw;
        if ((unsigned)tj < (unsigned)t &&
            (unsigned)hj < (unsigned)h &&
            (unsigned)wj < (unsigned)w) {
            j = (tj * h + hj) * w + wj;
        }
    }

    // ---- Phase 1: streaming fill with -FLT_MAX (evict-first) ----
    const float4 v = make_float4(NEG_F, NEG_F, NEG_F, NEG_F);
    #pragma unroll 8
    for (int f = tid; f < n4; f += 256) __stcs(row + f, v);

    __syncthreads();

    // ---- Phase 2: single store per candidate thread (default policy) ----
    if (j >= 0) ((float*)row)[j] = 0.0f;
}

// ---------------------------------------------------------------------------
extern "C" void kernel_launch(void* const* d_in, const int* in_sizes, int n_in,
                              void* d_out, int out_size) {
    const int N = (int)(sqrt((double)out_size) + 0.5);   // out is N*N floats

    const int* tp = (const int*)d_in[0];
    const int* hp = (const int*)d_in[1];
    const int* wp = (const int*)d_in[2];

    fused_mask_kernel<<<N, 256>>>(tp, hp, wp, (float4*)d_out, N);
}

// round 16
// speedup vs baseline: 1.0308x; 1.0252x over previous
#include <cuda_runtime.h>
#include <cstdint>
#include <math.h>

#define NEG_F (-3.402823466e+38f)   // jnp.finfo(float32).min == -FLT_MAX

// ---------------------------------------------------------------------------
// FINAL champion: one block per row i of the N x N mask (N = t*h*w).
//   Prologue: threads 0..130 load t/h/w and fully decode their candidate
//             column BEFORE the fill (latency overlaps the store stream).
//   Phase 1:  stream the row with -FLT_MAX via st.global.cs (evict-first) —
//             zero-reuse data; streaming hint smooths L2 writeback.
//   Phase 2:  after __syncthreads, candidate threads store 0.0f with default
//             policy (merges with the still-dirty L2 line; no extra DRAM).
// Masked columns per row:
//   - local window: dt,dh,dw in [-2,2]                      -> 125 candidates
//   - sparse pow2 {1,2,4} along exactly one axis (others 0) -> only +/-4 adds
//     new entries (1,2 lie inside the window)               ->   6 candidates
//
// Measured: ~37.2us kernel = 7.2 TB/s sustained stores (~90% of HBM spec;
// hard spec floor 33.5us for the mandatory 268 MB of output).
// Benched and rejected across the session: monolithic predicate (4x slower,
// ALU-issue-bound), separate fill+scatter kernels (cold-RMW on scatter),
// persistent single-wave grid (-27%, parallelism loss), cp.async.bulk S2G
// (-16%; the ~6300 B/cyc LTS cap is path-independent), STG.256 (neutral;
// issue was never binding), branch-free per-chunk classify (-6%; decode ALU
// exceeded scatter cost), 2 rows/block (neutral).
// This kernel is at the DRAM-write roofline.
// ---------------------------------------------------------------------------
__global__ void __launch_bounds__(256)
fused_mask_kernel(const int* __restrict__ tp, const int* __restrict__ hp,
                  const int* __restrict__ wp, float4* __restrict__ out4, int N) {
    const int i   = blockIdx.x;         // row index
    const int tid = threadIdx.x;
    const int n4  = N >> 2;             // float4s per row
    float4* row = out4 + (size_t)i * (size_t)n4;

    // ---- Prologue: decode candidate before the fill (tid < 131) ----
    int j = -1;                         // column to zero; -1 = none
    if (tid < 131) {
        const int t = *tp;
        const int h = *hp;
        const int w = *wp;

        const int wi = i % w;
        const int ri = i / w;
        const int hi = ri % h;
        const int ti = ri / h;

        int dt, dh, dw;
        if (tid < 125) {
            dt = tid / 25 - 2;
            dh = (tid / 5) % 5 - 2;
            dw = tid % 5 - 2;
        } else {
            const int s    = tid - 125;        // 0..5
            const int axis = s >> 1;           // 0:t 1:h 2:w
            const int off  = (s & 1) ? 4 : -4;
            dt = (axis == 0) ? off : 0;
            dh = (axis == 1) ? off : 0;
            dw = (axis == 2) ? off : 0;
        }

        const int tj = ti + dt;
        const int hj = hi + dh;
        const int wj = wi + dw;
        if ((unsigned)tj < (unsigned)t &&
            (unsigned)hj < (unsigned)h &&
            (unsigned)wj < (unsigned)w) {
            j = (tj * h + hj) * w + wj;
        }
    }

    // ---- Phase 1: streaming fill with -FLT_MAX (evict-first) ----
    const float4 v = make_float4(NEG_F, NEG_F, NEG_F, NEG_F);
    #pragma unroll 8
    for (int f = tid; f < n4; f += 256) __stcs(row + f, v);

    __syncthreads();

    // ---- Phase 2: single store per candidate thread (default policy) ----
    if (j >= 0) ((float*)row)[j] = 0.0f;
}

// ---------------------------------------------------------------------------
extern "C" void kernel_launch(void* const* d_in, const int* in_sizes, int n_in,
                              void* d_out, int out_size) {
    const int N = (int)(sqrt((double)out_size) + 0.5);   // out is N*N floats

    const int* tp = (const int*)d_in[0];
    const int* hp = (const int*)d_in[1];
    const int* wp = (const int*)d_in[2];

    fused_mask_kernel<<<N, 256>>>(tp, hp, wp, (float4*)d_out, N);
}